// round 8
// baseline (speedup 1.0000x reference)
#include <cuda_runtime.h>
#include <cuda_fp16.h>

#define HID 128
#define NS  12
#define PAD 132          // weight row pitch (elements)
#define NW  14           // warps per CTA
#define NB  8            // batch elements per warp-task
#define THREADS (NW*32)
#define GRID 148

typedef unsigned long long ull;

// ---- shared memory layout (float offsets) ----
#define OW0   0                      // W0^T  [12][132] fp32
#define OCEN  1584                   // 12 (pad 16)
#define OINV  1600                   // 12 (pad 16)
#define OW1H  1616                   // W1^T  [128][132] fp16  (8448 floats)
#define OW2H  10064                  // W2^T  [128][132] fp16  (8448 floats)
#define OWARP 18512
#define WSTRIDE 1536                 // BigA 1024 + V1h 512
#define SMEM_FLOATS (OWARP + NW*WSTRIDE)   // 40016 floats = 160064 B

__device__ float g_R3[HID];
__device__ float g_c3;

__global__ void init_kernel(const float* __restrict__ W3, const float* __restrict__ b3,
                            const float* __restrict__ Wout, const float* __restrict__ bout)
{
    int h = threadIdx.x;  // 0..127
    float acc = 0.f;
    for (int j = 0; j < HID; ++j) acc = fmaf(Wout[j], W3[j*HID + h], acc);
    g_R3[h] = acc;
    if (h == 0) {
        float c = bout[0];
        for (int j = 0; j < HID; ++j) c = fmaf(Wout[j], b3[j], c);
        g_c3 = c;
    }
}

// ---- packed f32x2 helpers ----
__device__ __forceinline__ ull ffma2(ull a, ull b, ull c)
{
    ull d;
    asm("fma.rn.f32x2 %0, %1, %2, %3;" : "=l"(d) : "l"(a), "l"(b), "l"(c));
    return d;
}
__device__ __forceinline__ ull pack2(float lo, float hi)
{
    ull d; asm("mov.b64 %0, {%1, %2};" : "=l"(d) : "f"(lo), "f"(hi)); return d;
}
__device__ __forceinline__ void unpack2(ull v, float& lo, float& hi)
{
    asm("mov.b64 {%0, %1}, %2;" : "=f"(lo), "=f"(hi) : "l"(v));
}
__device__ __forceinline__ ull shflx(ull v, int src)
{
    return __shfl_sync(0xffffffffu, v, src);
}

// Fast tanh: 1 - 2/(e^{2x}+1).
__device__ __forceinline__ float ftanh(float x)
{
    float e = __expf(2.0f * x);
    return 1.0f - __fdividef(2.0f, e + 1.0f);
}

// ---- bank swizzle for BigA [128][8] fp32 rows (32B rows) ----
__device__ __forceinline__ int physrow(int h) { return (h & ~3) | ((h ^ (h >> 2)) & 3); }
__device__ __forceinline__ int cswap(int h)   { return ((h >> 2) ^ (h >> 4)) & 1; }

__device__ __forceinline__ void store8(float* buf, int h, const float t[8])
{
    float* rp = buf + physrow(h)*8;
    int b = cswap(h);
    *(float4*)(rp + 4*b)     = make_float4(t[0], t[1], t[2], t[3]);
    *(float4*)(rp + 4*(b^1)) = make_float4(t[4], t[5], t[6], t[7]);
}

// ---- fp16 side buffer V1h: 16B rows, XOR layout (R4-proven patterns) ----
__device__ __forceinline__ int off16f(int h)   // float offset of 16B row
{
    return ((h & 3) * 32 + ((h >> 2) ^ (2 * (h & 3)))) * 4;
}

// unpack uint2 of half2s -> 4 floats
__device__ __forceinline__ void h4_to_f4(uint2 u, float w[4])
{
    float2 f01 = __half22float2(*(__half2*)&u.x);
    float2 f23 = __half22float2(*(__half2*)&u.y);
    w[0] = f01.x; w[1] = f01.y; w[2] = f23.x; w[3] = f23.y;
}

// Forward matvec, fp16 weights: z[j][pp] = bias[4l+j] + sum_k Wt[k][4l+j]*in[k][pp]
__device__ __forceinline__ void fwd2h(const __half* __restrict__ Wh,
                                      const float* __restrict__ biasg,
                                      const float* __restrict__ inq,
                                      ull z[4][4], int l)
{
    float4 bb = *(const float4*)&biasg[4*l];
    float bj[4] = {bb.x, bb.y, bb.z, bb.w};
#pragma unroll
    for (int j = 0; j < 4; ++j) {
        ull b2 = pack2(bj[j], bj[j]);
#pragma unroll
        for (int pp = 0; pp < 4; ++pp) z[j][pp] = b2;
    }

#pragma unroll 4
    for (int k = 0; k < HID; ++k) {
        uint2 u = *(const uint2*)&Wh[k*PAD + 4*l];      // 8B contiguous: 2 wf
        const float* rp = inq + physrow(k)*8;
        int b = cswap(k);
        ulonglong2 xa = *(const ulonglong2*)(rp + 4*b);
        ulonglong2 xb = *(const ulonglong2*)(rp + 4*(b^1));
        ull x[4] = {xa.x, xa.y, xb.x, xb.y};
        float wj[4];
        h4_to_f4(u, wj);
#pragma unroll
        for (int j = 0; j < 4; ++j) {
            ull w2 = pack2(wj[j], wj[j]);
#pragma unroll
            for (int pp = 0; pp < 4; ++pp)
                z[j][pp] = ffma2(w2, x[pp], z[j][pp]);
        }
    }
}

// Input-layer forward (K=12, fp32 W0), x pairs delivered by warp shuffles.
__device__ __forceinline__ void fwd2x(const float* __restrict__ Wt,
                                      const float* __restrict__ biasg,
                                      ull ua, ull ub, ull z[4][4], int l)
{
    float4 bb = *(const float4*)&biasg[4*l];
    float bj[4] = {bb.x, bb.y, bb.z, bb.w};
#pragma unroll
    for (int j = 0; j < 4; ++j) {
        ull b2 = pack2(bj[j], bj[j]);
#pragma unroll
        for (int pp = 0; pp < 4; ++pp) z[j][pp] = b2;
    }

#pragma unroll
    for (int k = 0; k < NS; ++k) {
        ull x[4];
#pragma unroll
        for (int pp = 0; pp < 4; ++pp)
            x[pp] = (k < 8) ? shflx(ua, 4*k + pp) : shflx(ub, 4*(k-8) + pp);
        float4 w4 = *(const float4*)&Wt[k*PAD + 4*l];
        float wj[4] = {w4.x, w4.y, w4.z, w4.w};
#pragma unroll
        for (int j = 0; j < 4; ++j) {
            ull w2 = pack2(wj[j], wj[j]);
#pragma unroll
            for (int pp = 0; pp < 4; ++pp)
                z[j][pp] = ffma2(w2, x[pp], z[j][pp]);
        }
    }
}

// Backward vecmat, fp16 weights: r[m][pp] = sum_h g[h][pp] * Wt[(l+32m)][h]
__device__ __forceinline__ void bwd2h(const __half* __restrict__ Wh,
                                      const float* __restrict__ gin,
                                      ull r[4][4], int l)
{
#pragma unroll
    for (int m = 0; m < 4; ++m)
#pragma unroll
        for (int pp = 0; pp < 4; ++pp) r[m][pp] = 0ull;

#pragma unroll 2
    for (int c = 0; c < 32; ++c) {          // chunks of 4 h-rows
        int perm = c & 3, b = (c ^ (c >> 2)) & 1;
        ull g[4][4];
#pragma unroll
        for (int sg = 0; sg < 4; ++sg) {
            const float* rp = gin + (4*c + (sg ^ perm))*8;   // = physrow(4c+sg)
            ulonglong2 ga = *(const ulonglong2*)(rp + 4*b);
            ulonglong2 gb = *(const ulonglong2*)(rp + 4*(b^1));
            g[sg][0] = ga.x; g[sg][1] = ga.y; g[sg][2] = gb.x; g[sg][3] = gb.y;
        }
#pragma unroll
        for (int m = 0; m < 4; ++m) {
            // 8B load, 264B lane pitch: banks 2l..2l+1 per 16-lane phase -> 2 wf
            uint2 u = *(const uint2*)&Wh[(l + 32*m)*PAD + 4*c];
            float wm[4];
            h4_to_f4(u, wm);
#pragma unroll
            for (int sg = 0; sg < 4; ++sg) {
                ull w2 = pack2(wm[sg], wm[sg]);
#pragma unroll
                for (int pp = 0; pp < 4; ++pp)
                    r[m][pp] = ffma2(w2, g[sg][pp], r[m][pp]);
            }
        }
    }
}

__global__ __launch_bounds__(THREADS, 1)
void mlp_kernel(const float* __restrict__ state,
                const float* __restrict__ safe_m, const float* __restrict__ safe_l,
                const float* __restrict__ W0, const float* __restrict__ b0,
                const float* __restrict__ W1, const float* __restrict__ b1,
                const float* __restrict__ W2, const float* __restrict__ b2,
                float* __restrict__ out, int nb)
{
    extern __shared__ float s[];
    __half* W1h = (__half*)(s + OW1H);
    __half* W2h = (__half*)(s + OW2H);
    int tid = threadIdx.x;

    // ---- stage weights into SMEM (transposed, PAD-pitched; W1/W2 as fp16) ----
    for (int i = tid; i < HID*HID; i += THREADS) {
        int h = i >> 7, k = i & 127;
        W1h[k*PAD + h] = __float2half_rn(W1[i]);
        W2h[k*PAD + h] = __float2half_rn(W2[i]);
    }
    for (int i = tid; i < HID*NS; i += THREADS) {
        int h = i / NS, k = i - h*NS;
        s[OW0 + k*PAD + h] = W0[i];
    }
    if (tid < NS) {
        float m = safe_m[tid], lo = safe_l[tid];
        s[OCEN + tid] = 0.5f * (m + lo);
        s[OINV + tid] = 2.0f / (m - lo);
    }
    __syncthreads();

    int w = tid >> 5, l = tid & 31;
    float* BigA = s + OWARP + w*WSTRIDE;     // [128][8] fp32 swizzled: V0->V1->g2->g1->g0
    float* V1h  = BigA + 1024;               // fp16 rows, XOR layout

    int gw = blockIdx.x + GRID * w;          // warp-major: one task per warp
    int quads = (nb + NB - 1) / NB;
    if (gw < quads) {
        int base = gw * NB;

        // ---- A: load + normalize inputs into 2 register pairs per lane ----
        ull ua, ub;
        {
            int p0 = 2*(l & 3);
            int ka = l >> 2;                  // 0..7
            int kb = 8 + ((l >> 2) & 3);      // 8..11
            int i0 = base + p0, i1 = base + p0 + 1;
            float a0 = (i0 < nb) ? state[i0*NS + ka] : 0.f;
            float a1 = (i1 < nb) ? state[i1*NS + ka] : 0.f;
            float c0 = (i0 < nb) ? state[i0*NS + kb] : 0.f;
            float c1 = (i1 < nb) ? state[i1*NS + kb] : 0.f;
            float ca = s[OCEN + ka], ia = s[OINV + ka];
            float cb = s[OCEN + kb], ib = s[OINV + kb];
            ua = pack2((a0 - ca)*ia, (a1 - ca)*ia);
            ub = pack2((c0 - cb)*ib, (c1 - cb)*ib);
        }

        ull z[4][4];
        float t[8];

        // ---- B: input layer (K=12, shfl x) + tanh -> V0 (BigA) ----
        fwd2x(s + OW0, b0, ua, ub, z, l);
#pragma unroll
        for (int j = 0; j < 4; ++j) {
#pragma unroll
            for (int pp = 0; pp < 4; ++pp) unpack2(z[j][pp], t[2*pp], t[2*pp+1]);
#pragma unroll
            for (int p = 0; p < 8; ++p) t[p] = ftanh(t[p]);
            store8(BigA, 4*l + j, t);
        }
        __syncwarp();

        // ---- C: layer 1 + tanh -> V1 (BigA, in place) + fp16 copy (V1h) ----
        fwd2h(W1h, b1, BigA, z, l);
        __syncwarp();                        // all reads of V0 done before overwrite
#pragma unroll
        for (int j = 0; j < 4; ++j) {
#pragma unroll
            for (int pp = 0; pp < 4; ++pp) unpack2(z[j][pp], t[2*pp], t[2*pp+1]);
#pragma unroll
            for (int p = 0; p < 8; ++p) t[p] = ftanh(t[p]);
            store8(BigA, 4*l + j, t);
            __half2 h0 = __floats2half2_rn(t[0], t[1]);
            __half2 h1 = __floats2half2_rn(t[2], t[3]);
            __half2 h2 = __floats2half2_rn(t[4], t[5]);
            __half2 h3 = __floats2half2_rn(t[6], t[7]);
            uint4 u;
            u.x = *(unsigned*)&h0; u.y = *(unsigned*)&h1;
            u.z = *(unsigned*)&h2; u.w = *(unsigned*)&h3;
            *(uint4*)&V1h[off16f(4*l + j)] = u;
        }
        __syncwarp();

        // ---- D: layer 2 + tanh; vout = R3.V2 (output); g2 -> BigA ----
        fwd2h(W2h, b2, BigA, z, l);
        __syncwarp();                        // V1 reads complete
        {
            ull vo[4] = {0ull, 0ull, 0ull, 0ull};
            float4 r4 = *(const float4*)&g_R3[4*l];
            float rj[4] = {r4.x, r4.y, r4.z, r4.w};
#pragma unroll
            for (int j = 0; j < 4; ++j) {
                ull rj2 = pack2(rj[j], rj[j]);
#pragma unroll
                for (int pp = 0; pp < 4; ++pp) unpack2(z[j][pp], t[2*pp], t[2*pp+1]);
#pragma unroll
                for (int p = 0; p < 8; ++p) t[p] = ftanh(t[p]);
#pragma unroll
                for (int pp = 0; pp < 4; ++pp)
                    vo[pp] = ffma2(rj2, pack2(t[2*pp], t[2*pp+1]), vo[pp]);
                float gq[8];
#pragma unroll
                for (int p = 0; p < 8; ++p) gq[p] = rj[j] * (1.f - t[p]*t[p]);
                store8(BigA, 4*l + j, gq);
            }
            float vout[8];
#pragma unroll
            for (int pp = 0; pp < 4; ++pp) unpack2(vo[pp], vout[2*pp], vout[2*pp+1]);
#pragma unroll
            for (int p = 0; p < 8; ++p) {
                float v = vout[p];
#pragma unroll
                for (int off = 16; off > 0; off >>= 1)
                    v += __shfl_xor_sync(0xffffffffu, v, off);
                vout[p] = v;
            }
            if (l == 0) {
                float c3 = g_c3;
#pragma unroll
                for (int p = 0; p < 8; ++p)
                    if (base + p < nb) out[(base + p)*13] = vout[p] + c3;
            }
        }
        __syncwarp();

        ull r[4][4];

        // ---- E: r = g2.W2 ; s1 from fp16 copy; g1 -> BigA ----
        bwd2h(W2h, BigA, r, l);
        __syncwarp();
#pragma unroll
        for (int m = 0; m < 4; ++m) {
            uint4 u = *(const uint4*)&V1h[off16f(l + 32*m)];
            float2 f0 = __half22float2(*(__half2*)&u.x);
            float2 f1 = __half22float2(*(__half2*)&u.y);
            float2 f2 = __half22float2(*(__half2*)&u.z);
            float2 f3 = __half22float2(*(__half2*)&u.w);
            float vp[8] = {f0.x, f0.y, f1.x, f1.y, f2.x, f2.y, f3.x, f3.y};
            float gq[8];
#pragma unroll
            for (int pp = 0; pp < 4; ++pp) {
                float r0, r1; unpack2(r[m][pp], r0, r1);
                gq[2*pp]   = r0 * (1.f - vp[2*pp]*vp[2*pp]);
                gq[2*pp+1] = r1 * (1.f - vp[2*pp+1]*vp[2*pp+1]);
            }
            store8(BigA, l + 32*m, gq);
        }
        __syncwarp();

        // ---- F: s0 recomputed from register x (shfl); r = g1.W1 ; g0 -> BigA ----
        float s0[4][8];
        {
            ull z0[4][4];
#pragma unroll
            for (int m = 0; m < 4; ++m) {
                float bm = b0[l + 32*m];
                ull b2 = pack2(bm, bm);
#pragma unroll
                for (int pp = 0; pp < 4; ++pp) z0[m][pp] = b2;
            }
#pragma unroll
            for (int k = 0; k < NS; ++k) {
                ull x[4];
#pragma unroll
                for (int pp = 0; pp < 4; ++pp)
                    x[pp] = (k < 8) ? shflx(ua, 4*k + pp) : shflx(ub, 4*(k-8) + pp);
#pragma unroll
                for (int m = 0; m < 4; ++m) {
                    float wv = s[OW0 + k*PAD + l + 32*m];
                    ull w2 = pack2(wv, wv);
#pragma unroll
                    for (int pp = 0; pp < 4; ++pp)
                        z0[m][pp] = ffma2(w2, x[pp], z0[m][pp]);
                }
            }
#pragma unroll
            for (int m = 0; m < 4; ++m)
#pragma unroll
                for (int pp = 0; pp < 4; ++pp) {
                    float a, b; unpack2(z0[m][pp], a, b);
                    a = ftanh(a); b = ftanh(b);
                    s0[m][2*pp]   = 1.f - a*a;
                    s0[m][2*pp+1] = 1.f - b*b;
                }
        }
        bwd2h(W1h, BigA, r, l);
        __syncwarp();
#pragma unroll
        for (int m = 0; m < 4; ++m) {
            float gq[8];
#pragma unroll
            for (int pp = 0; pp < 4; ++pp) {
                float r0, r1; unpack2(r[m][pp], r0, r1);
                gq[2*pp]   = r0 * s0[m][2*pp];
                gq[2*pp+1] = r1 * s0[m][2*pp+1];
            }
            store8(BigA, l + 32*m, gq);
        }
        __syncwarp();

        // ---- final: J[k][p] = (sum_h g0[h][p] * W0t[k][h]) * inv[k] ----
        {
            int p  = l & 7;
            int k0 = l >> 3;                 // k = k0 + 4c, c in 0..2
            int psel = p >> 2, pw = p & 3;
            float acc[3] = {0.f, 0.f, 0.f};
#pragma unroll 2
            for (int i = 0; i < 32; ++i) {   // h = 4i..4i+3
                float4 w0 = *(const float4*)&s[OW0 + (k0    )*PAD + 4*i];
                float4 w1 = *(const float4*)&s[OW0 + (k0 + 4)*PAD + 4*i];
                float4 w2 = *(const float4*)&s[OW0 + (k0 + 8)*PAD + 4*i];
                float gv[4];
#pragma unroll
                for (int d = 0; d < 4; ++d) {
                    int h = 4*i + d;
                    gv[d] = BigA[physrow(h)*8 + 4*(psel ^ cswap(h)) + pw];
                }
                acc[0] = fmaf(w0.x, gv[0], acc[0]); acc[0] = fmaf(w0.y, gv[1], acc[0]);
                acc[0] = fmaf(w0.z, gv[2], acc[0]); acc[0] = fmaf(w0.w, gv[3], acc[0]);
                acc[1] = fmaf(w1.x, gv[0], acc[1]); acc[1] = fmaf(w1.y, gv[1], acc[1]);
                acc[1] = fmaf(w1.z, gv[2], acc[1]); acc[1] = fmaf(w1.w, gv[3], acc[1]);
                acc[2] = fmaf(w2.x, gv[0], acc[2]); acc[2] = fmaf(w2.y, gv[1], acc[2]);
                acc[2] = fmaf(w2.z, gv[2], acc[2]); acc[2] = fmaf(w2.w, gv[3], acc[2]);
            }
            if (base + p < nb) {
#pragma unroll
                for (int c = 0; c < 3; ++c) {
                    int k = k0 + 4*c;
                    out[(base + p)*13 + 1 + k] = acc[c] * s[OINV + k];
                }
            }
        }
    }
}

extern "C" void kernel_launch(void* const* d_in, const int* in_sizes, int n_in,
                              void* d_out, int out_size)
{
    const float* state  = (const float*)d_in[0];
    const float* safe_m = (const float*)d_in[1];
    const float* safe_l = (const float*)d_in[2];
    const float* W0     = (const float*)d_in[3];
    const float* b0     = (const float*)d_in[4];
    const float* W1     = (const float*)d_in[5];
    const float* b1     = (const float*)d_in[6];
    const float* W2     = (const float*)d_in[7];
    const float* b2     = (const float*)d_in[8];
    const float* W3     = (const float*)d_in[9];
    const float* b3     = (const float*)d_in[10];
    const float* Wout   = (const float*)d_in[11];
    const float* bout   = (const float*)d_in[12];
    float* out = (float*)d_out;

    int nb = in_sizes[0] / NS;

    cudaFuncSetAttribute(mlp_kernel, cudaFuncAttributeMaxDynamicSharedMemorySize,
                         SMEM_FLOATS * (int)sizeof(float));

    init_kernel<<<1, HID>>>(W3, b3, Wout, bout);
    mlp_kernel<<<GRID, THREADS, SMEM_FLOATS * sizeof(float)>>>(
        state, safe_m, safe_l, W0, b0, W1, b1, W2, b2, out, nb);
}